// round 8
// baseline (speedup 1.0000x reference)
#include <cuda_runtime.h>
#include <cstdint>

#define N_ 100000
#define E_ 3200000
#define NCAND 1024
#define CAP 4096
#define SCAN_B 256
#define NBLK ((N_ + SCAN_B - 1) / SCAN_B)   // 391

// ---------------- device scratch (static, no runtime allocation) ----------------
__device__ float2 g_fst [N_*32];
__device__ float2 g_emb1[N_*32];
__device__ uint2  g_edge[E_];          // CSR records: (col, val bits), segmented
__device__ unsigned char g_cls[E_];    // 0 = m12, 1 = m1-only, 2 = dropped
__device__ float  g_order0[N_];
__device__ float  g_order1[N_];
__device__ float  g_num1[N_];
__device__ unsigned g_cnt[N_];         // packed: deg | cnt_m1<<10 | cnt_m12<<20
__device__ unsigned g_cursor[N_];      // packed per-class cursors
__device__ uint2  g_rowseg[N_];        // .x = rowptr, .y = cnt12 | cnt1<<10 | deg<<20
__device__ unsigned g_scanstate[NBLK]; // 0=empty, 1<<30|agg, 2<<30|prefix
__device__ unsigned g_keys[N_];
__device__ unsigned g_hist64[65536];
__device__ unsigned g_prefix;
__device__ int g_ticket;
__device__ int g_ticket3;
__device__ int g_selcount;
__device__ unsigned long long g_cand[CAP];

// ---------------- Threefry-2x32 (20 rounds, 5 key injections) -------------------
#define TFR(a,b,r) { a += b; b = ((b << (r)) | (b >> (32-(r)))); b ^= a; }

__host__ __device__ __forceinline__ void tf2x32(unsigned k0, unsigned k1,
                                                unsigned& x0, unsigned& x1) {
    unsigned k2 = k0 ^ k1 ^ 0x1BD11BDAu;
    x0 += k0; x1 += k1;
    TFR(x0,x1,13) TFR(x0,x1,15) TFR(x0,x1,26) TFR(x0,x1,6)
    x0 += k1; x1 += k2 + 1u;
    TFR(x0,x1,17) TFR(x0,x1,29) TFR(x0,x1,16) TFR(x0,x1,24)
    x0 += k2; x1 += k0 + 2u;
    TFR(x0,x1,13) TFR(x0,x1,15) TFR(x0,x1,26) TFR(x0,x1,6)
    x0 += k0; x1 += k1 + 3u;
    TFR(x0,x1,17) TFR(x0,x1,29) TFR(x0,x1,16) TFR(x0,x1,24)
    x0 += k1; x1 += k2 + 4u;
    TFR(x0,x1,13) TFR(x0,x1,15) TFR(x0,x1,26) TFR(x0,x1,6)
    x0 += k2; x1 += k0 + 5u;
}

static void jax_split_part(unsigned k0, unsigned k1, unsigned* nk, unsigned* sk) {
    unsigned a0 = 0u, a1 = 0u; tf2x32(k0, k1, a0, a1);
    unsigned b0 = 0u, b1 = 1u; tf2x32(k0, k1, b0, b1);
    nk[0] = a0; nk[1] = a1;
    sk[0] = b0; sk[1] = b1;
}

__device__ __forceinline__ unsigned rb32(unsigned k0, unsigned k1, unsigned i) {
    unsigned x0 = 0u, x1 = i;
    tf2x32(k0, k1, x0, x1);
    return x0 ^ x1;
}

// ---------------- kernels -------------------------------------------------------

__global__ void k_zero() {
    int i = blockIdx.x * blockDim.x + threadIdx.x;
    if (i < N_) { g_cnt[i] = 0u; g_cursor[i] = 0u; }
    if (i < 65536) g_hist64[i] = 0u;
    if (i < NBLK) g_scanstate[i] = 0u;
    if (i == 0) {
        g_prefix = 0u; g_selcount = 0; g_ticket = 0; g_ticket3 = 0;
    }
}

// RNG masks (stored) + packed per-row class counts (single atomic per edge)
__global__ void k_count(const int* __restrict__ rows,
                        unsigned a0, unsigned a1, unsigned b0, unsigned b1) {
    int e = blockIdx.x * blockDim.x + threadIdx.x;
    if (e >= E_) return;
    unsigned u1 = rb32(a0, a1, (unsigned)e);
    unsigned u2 = rb32(b0, b1, (unsigned)e);
    unsigned m1  = (u1 >= 0x80000000u) ? 1u : 0u;           // keep prob 0.5
    unsigned m12 = (m1 && u2 >= 0xC0000000u) ? 1u : 0u;     // joint keep
    g_cls[e] = (unsigned char)(m12 ? 0 : (m1 ? 1 : 2));
    int r = __ldg(rows + e);
    atomicAdd(&g_cnt[r], 1u + (m1 << 10) + (m12 << 20));
}

// ---- single-kernel decoupled-lookback scan over degrees -> g_rowseg ----
// All NBLK=391 blocks are simultaneously resident (100K threads), so a
// blockIdx-ordered lookback cannot deadlock.
__global__ void k_scan() {
    __shared__ int s[SCAN_B];
    __shared__ unsigned s_base;
    int tid = threadIdx.x;
    int bid = blockIdx.x;
    int i = bid * SCAN_B + tid;
    unsigned pc = (i < N_) ? g_cnt[i] : 0u;
    int d = (int)(pc & 1023u);
    s[tid] = d;
    __syncthreads();
    for (int off = 1; off < SCAN_B; off <<= 1) {
        int v = s[tid];
        if (tid >= off) v += s[tid - off];
        __syncthreads();
        s[tid] = v;
        __syncthreads();
    }
    int total = s[SCAN_B - 1];

    if (tid == 0) {
        unsigned base = 0u;
        if (bid == 0) {
            __threadfence();
            g_scanstate[0] = (2u << 30) | (unsigned)total;
        } else {
            // publish aggregate
            __threadfence();
            g_scanstate[bid] = (1u << 30) | (unsigned)total;
            // lookback
            int j = bid - 1;
            while (j >= 0) {
                unsigned st = *((volatile unsigned*)&g_scanstate[j]);
                unsigned flag = st >> 30;
                if (flag == 0u) continue;               // spin
                base += st & 0x3FFFFFFFu;
                if (flag == 2u) break;                  // inclusive prefix found
                --j;
            }
            __threadfence();
            g_scanstate[bid] = (2u << 30) | (base + (unsigned)total);
        }
        s_base = base;
    }
    __syncthreads();

    if (i < N_) {
        unsigned rp = s_base + (unsigned)(s[tid] - d);
        unsigned cnt1  = (pc >> 10) & 1023u;
        unsigned cnt12 = (pc >> 20) & 1023u;
        g_rowseg[i] = make_uint2(rp, cnt12 | (cnt1 << 10) | ((unsigned)d << 20));
    }
}

// scatter edges into segmented CSR slots: [m12][m1-only][dropped]
__global__ void k_fill(const int* __restrict__ rows, const int* __restrict__ cols,
                       const float* __restrict__ vals) {
    int e = blockIdx.x * blockDim.x + threadIdx.x;
    if (e >= E_) return;
    int cls = (int)g_cls[e];

    int r = __ldg(rows + e);
    uint2 rs = __ldg(&g_rowseg[r]);
    unsigned old = atomicAdd(&g_cursor[r], 1u << (10 * cls));
    unsigned within = (old >> (10 * cls)) & 1023u;
    unsigned cnt12 = rs.y & 1023u;
    unsigned cnt1  = (rs.y >> 10) & 1023u;
    unsigned segbase = (cls == 0) ? 0u : ((cls == 1) ? cnt12 : cnt1);
    int pos = (int)(rs.x + segbase + within);
    g_edge[pos] = make_uint2((unsigned)__ldg(cols + e), __float_as_uint(__ldg(vals + e)));
}

// ---- gather SpMM passes: 1 warp per row, float2 per lane ----
// PASS 1: xin=embeds, out fst = sum - embeds[r]; order0 = sum v
// PASS 2: xin=fst (first cnt1), out emb1 = sum - (1+order0)*fst; num1, order1
// PASS 3: xin=emb1 (first cnt12), fused scoring + histogram; last block finds
//         the exact 16-bit top-1024 threshold from the 64K-bin histogram.
template<int PASS>
__global__ void k_pass(const float2* __restrict__ embeds, float* __restrict__ out,
                       unsigned n0, unsigned n1) {
    unsigned t = blockIdx.x * blockDim.x + threadIdx.x;
    int w = (int)(t >> 5);
    int c = (int)(t & 31u);

    if (w < N_) {
        const float2* xin = (PASS == 1) ? embeds : (PASS == 2 ? g_fst : g_emb1);
        const float* numin = (PASS == 2) ? g_order0 : g_num1;

        uint2 rs = __ldg(&g_rowseg[w]);
        int beg = (int)rs.x;
        int cnt = (PASS == 1) ? (int)((rs.y >> 20) & 1023u)
                : (PASS == 2) ? (int)((rs.y >> 10) & 1023u)
                              : (int)(rs.y & 1023u);

        float ax = 0.f, ay = 0.f;
        float ns = 0.f, o1acc = 0.f;

        #pragma unroll 4
        for (int e = beg; e < beg + cnt; ++e) {
            uint2 er = __ldg(&g_edge[e]);
            float v = __uint_as_float(er.y);
            float2 x = __ldg(&xin[(size_t)er.x * 32 + c]);
            ax += v * x.x; ay += v * x.y;
            if (PASS == 1) ns += v;
            else           ns += v * __ldg(&numin[er.x]);
            if (PASS == 2) o1acc += v;
        }

        size_t idx = (size_t)w * 32 + c;

        if (PASS == 1) {
            float2 b = __ldg(&embeds[idx]);
            g_fst[idx] = make_float2(ax - b.x, ay - b.y);
            if (c == 0) g_order0[w] = ns;
        } else if (PASS == 2) {
            float o = __ldg(&g_order0[w]);
            float f = 1.0f + o;
            float2 p = __ldg(&g_fst[idx]);
            g_emb1[idx] = make_float2(ax - f * p.x, ay - f * p.y);
            if (c == 0) { g_num1[w] = ns - 2.0f * o; g_order1[w] = o1acc; }
        } else {
            float o1  = __ldg(&g_order1[w]);
            float o0  = __ldg(&g_order0[w]);
            float n1v = __ldg(&g_num1[w]);
            float f = 1.0f + o1;
            float2 e1 = __ldg(&g_emb1[idx]);
            float2 p  = __ldg(&g_fst[idx]);
            float2 b  = __ldg(&embeds[idx]);
            float e2x = ax - f * e1.x, e2y = ay - f * e1.y;
            float num2 = ns - n1v - o1;
            float inv = 1.0f / (o0 + n1v + num2 + 1e-8f);
            float sx = (p.x + e1.x + e2x) * inv;
            float sy = (p.y + e1.y + e2y) * inv;
            float sa = sx * sx + sy * sy;
            float sb = b.x * b.x + b.y * b.y;
            float dp = sx * b.x + sy * b.y;
            for (int off = 16; off > 0; off >>= 1) {
                sa += __shfl_down_sync(0xFFFFFFFFu, sa, off);
                sb += __shfl_down_sync(0xFFFFFFFFu, sb, off);
                dp += __shfl_down_sync(0xFFFFFFFFu, dp, off);
            }
            if (c == 0) {
                float na = sqrtf(sa); if (na < 1e-12f) na = 1e-12f;
                float nb = sqrtf(sb); if (nb < 1e-12f) nb = 1e-12f;
                float score = dp / (na * nb);
                unsigned bits = rb32(n0, n1, (unsigned)w);
                float u = __uint_as_float(0x3F800000u | (bits >> 9)) - 1.0f;
                score += -logf(-logf(u));
                out[w] = score;
                unsigned kk = __float_as_uint(score);
                kk = (kk & 0x80000000u) ? ~kk : (kk | 0x80000000u);
                g_keys[w] = kk;
                atomicAdd(&g_hist64[kk >> 16], 1u);
            }
        }
    }

    // ---- PASS 3 only: last-block threshold finder ----
    if (PASS == 3) {
        __shared__ int s_last;
        int tid = threadIdx.x;
        __threadfence();
        __syncthreads();
        if (tid == 0)
            s_last = (atomicAdd(&g_ticket3, 1) == (int)gridDim.x - 1) ? 1 : 0;
        __syncthreads();
        if (!s_last) return;

        // 256 threads: superbin sums (256 superbins x 256 bins), coalesced per warp
        __shared__ unsigned sup[256 + 1];
        __shared__ unsigned bins[256 + 1];
        __shared__ int s_star;
        int wid = tid >> 5, lane = tid & 31;
        for (int sb = wid; sb < 256; sb += 8) {
            unsigned acc = 0u;
            #pragma unroll
            for (int j = 0; j < 8; j++)
                acc += *((volatile unsigned*)&g_hist64[sb * 256 + lane + 32 * j]);
            for (int off = 16; off > 0; off >>= 1)
                acc += __shfl_down_sync(0xFFFFFFFFu, acc, off);
            if (lane == 0) sup[sb] = acc;
        }
        if (tid == 0) sup[256] = 0u;
        __syncthreads();
        // inclusive suffix sum over superbins
        for (int off = 1; off < 256; off <<= 1) {
            unsigned v = sup[tid] + ((tid + off < 256) ? sup[tid + off] : 0u);
            __syncthreads();
            sup[tid] = v;
            __syncthreads();
        }
        {
            unsigned here = sup[tid];
            unsigned next = (tid < 255) ? sup[tid + 1] : 0u;
            if (here >= NCAND && next < NCAND) s_star = tid;
        }
        __syncthreads();
        int ss = s_star;
        unsigned above = (ss < 255) ? sup[ss + 1] : 0u;   // count strictly above superbin
        bins[tid] = *((volatile unsigned*)&g_hist64[ss * 256 + tid]);
        __syncthreads();
        // inclusive suffix sum over the 256 bins of superbin ss
        for (int off = 1; off < 256; off <<= 1) {
            unsigned v = bins[tid] + ((tid + off < 256) ? bins[tid + off] : 0u);
            __syncthreads();
            bins[tid] = v;
            __syncthreads();
        }
        {
            unsigned here = above + bins[tid];
            unsigned next = above + ((tid < 255) ? bins[tid + 1] : 0u);
            if (here >= NCAND && next < NCAND)
                g_prefix = ((unsigned)(ss * 256 + tid)) << 16;
        }
    }
}

// ---- fused select + sort: grid selects candidates; last block bitonic-sorts ----
__global__ void k_selsort(float* __restrict__ out) {
    __shared__ unsigned long long sm[CAP];
    __shared__ int s_last;
    int tid = threadIdx.x;
    unsigned pref = g_prefix;                  // 16-bit threshold prefix (low bits 0)

    int i = blockIdx.x * blockDim.x + tid;
    if (i < N_) {
        unsigned k = g_keys[i];
        if (k >= pref) {
            int p = atomicAdd(&g_selcount, 1);
            if (p < CAP)
                g_cand[p] = (((unsigned long long)k) << 32) | (unsigned)(~(unsigned)i);
        }
    }
    __threadfence();
    __syncthreads();
    if (tid == 0)
        s_last = (atomicAdd(&g_ticket, 1) == (int)gridDim.x - 1) ? 1 : 0;
    __syncthreads();
    if (!s_last) return;

    int cnt = *((volatile int*)&g_selcount); if (cnt > CAP) cnt = CAP;
    for (int s = 0; s < CAP / 1024; s++) {
        int j = tid + s * 1024;
        sm[j] = (j < cnt) ? *((volatile unsigned long long*)&g_cand[j]) : 0ull;
    }
    __syncthreads();
    for (int k = 2; k <= CAP; k <<= 1) {
        for (int j = k >> 1; j > 0; j >>= 1) {
            for (int s = 0; s < CAP / 1024; s++) {
                int a = tid + s * 1024;
                int l = a ^ j;
                if (l > a) {
                    unsigned long long va = sm[a], vb = sm[l];
                    bool up = ((a & k) == 0);
                    if ((va < vb) == up) { sm[a] = vb; sm[l] = va; }
                }
            }
            __syncthreads();
        }
    }
    unsigned idx = ~((unsigned)sm[tid]);
    out[N_ + tid] = (float)idx;
}

// ---------------- launch --------------------------------------------------------
extern "C" void kernel_launch(void* const* d_in, const int* in_sizes, int n_in,
                              void* d_out, int out_size) {
    const int*   rows   = (const int*)d_in[0];
    const int*   cols   = (const int*)d_in[1];
    const float* vals   = (const float*)d_in[2];
    const float* embeds = (const float*)d_in[3];
    float* out = (float*)d_out;

    // key chain (partitionable): key(42) -> (split) kd1 -> (split) kd2 -> (split) kn
    unsigned k0 = 0u, k1 = 42u, nk[2], kd1[2], kd2[2], kn[2];
    jax_split_part(k0, k1, nk, kd1); k0 = nk[0]; k1 = nk[1];
    jax_split_part(k0, k1, nk, kd2); k0 = nk[0]; k1 = nk[1];
    jax_split_part(k0, k1, nk, kn);

    const int B = 256;
    const int gN   = (N_ + B - 1) / B;
    const int gN32 = (N_ * 32 + B - 1) / B;
    const int gE   = (E_ + B - 1) / B;
    const int gS   = (N_ + 1023) / 1024;

    k_zero<<<gN, B>>>();
    k_count<<<gE, B>>>(rows, kd1[0], kd1[1], kd2[0], kd2[1]);
    k_scan<<<NBLK, SCAN_B>>>();
    k_fill<<<gE, B>>>(rows, cols, vals);      // <- profiled launch (index 3)

    k_pass<1><<<gN32, B>>>((const float2*)embeds, out, kn[0], kn[1]);
    k_pass<2><<<gN32, B>>>((const float2*)embeds, out, kn[0], kn[1]);
    k_pass<3><<<gN32, B>>>((const float2*)embeds, out, kn[0], kn[1]);

    k_selsort<<<gS, 1024>>>(out);
}

// round 9
// speedup vs baseline: 1.0375x; 1.0375x over previous
#include <cuda_runtime.h>
#include <cstdint>

#define N_ 100000
#define E_ 3200000
#define NCAND 1024
#define CAP 4096
#define SCAN_B 256
#define NBLK ((N_ + SCAN_B - 1) / SCAN_B)   // 391

// ---------------- device scratch (static, no runtime allocation) ----------------
__device__ float2 g_fst [N_*32];
__device__ float2 g_emb1[N_*32];
__device__ uint2  g_edge[E_];          // CSR records: (col, val bits), segmented
__device__ unsigned char g_cls[E_];    // 0 = m12, 1 = m1-only, 2 = dropped
__device__ float  g_order0[N_];
__device__ float  g_order1[N_];
__device__ float  g_num1[N_];
__device__ unsigned g_cnt[N_];         // packed: deg | cnt_m1<<10 | cnt_m12<<20
__device__ unsigned g_cursor[N_];      // packed per-class cursors
__device__ uint2  g_rowseg[N_];        // .x = rowptr, .y = cnt12 | cnt1<<10 | deg<<20
__device__ int    g_blocktot[NBLK];    // per-block aggregates
__device__ unsigned g_scanstate[NBLK]; // 0 = pending, (1<<31)|prefix when ready
__device__ unsigned g_keys[N_];
__device__ unsigned g_hist64[65536];
__device__ unsigned g_prefix;
__device__ int g_ticket;
__device__ int g_ticket2;
__device__ int g_ticket3;
__device__ int g_selcount;
__device__ unsigned long long g_cand[CAP];

// ---------------- Threefry-2x32 (20 rounds, 5 key injections) -------------------
#define TFR(a,b,r) { a += b; b = ((b << (r)) | (b >> (32-(r)))); b ^= a; }

__host__ __device__ __forceinline__ void tf2x32(unsigned k0, unsigned k1,
                                                unsigned& x0, unsigned& x1) {
    unsigned k2 = k0 ^ k1 ^ 0x1BD11BDAu;
    x0 += k0; x1 += k1;
    TFR(x0,x1,13) TFR(x0,x1,15) TFR(x0,x1,26) TFR(x0,x1,6)
    x0 += k1; x1 += k2 + 1u;
    TFR(x0,x1,17) TFR(x0,x1,29) TFR(x0,x1,16) TFR(x0,x1,24)
    x0 += k2; x1 += k0 + 2u;
    TFR(x0,x1,13) TFR(x0,x1,15) TFR(x0,x1,26) TFR(x0,x1,6)
    x0 += k0; x1 += k1 + 3u;
    TFR(x0,x1,17) TFR(x0,x1,29) TFR(x0,x1,16) TFR(x0,x1,24)
    x0 += k1; x1 += k2 + 4u;
    TFR(x0,x1,13) TFR(x0,x1,15) TFR(x0,x1,26) TFR(x0,x1,6)
    x0 += k2; x1 += k0 + 5u;
}

static void jax_split_part(unsigned k0, unsigned k1, unsigned* nk, unsigned* sk) {
    unsigned a0 = 0u, a1 = 0u; tf2x32(k0, k1, a0, a1);
    unsigned b0 = 0u, b1 = 1u; tf2x32(k0, k1, b0, b1);
    nk[0] = a0; nk[1] = a1;
    sk[0] = b0; sk[1] = b1;
}

__device__ __forceinline__ unsigned rb32(unsigned k0, unsigned k1, unsigned i) {
    unsigned x0 = 0u, x1 = i;
    tf2x32(k0, k1, x0, x1);
    return x0 ^ x1;
}

// ---------------- kernels -------------------------------------------------------

__global__ void k_zero() {
    int i = blockIdx.x * blockDim.x + threadIdx.x;
    if (i < N_) { g_cnt[i] = 0u; g_cursor[i] = 0u; }
    if (i < 65536) g_hist64[i] = 0u;
    if (i < NBLK) g_scanstate[i] = 0u;
    if (i == 0) {
        g_prefix = 0u; g_selcount = 0; g_ticket = 0; g_ticket2 = 0; g_ticket3 = 0;
    }
}

// RNG masks (stored) + packed per-row class counts (single atomic per edge)
__global__ void k_count(const int* __restrict__ rows,
                        unsigned a0, unsigned a1, unsigned b0, unsigned b1) {
    int e = blockIdx.x * blockDim.x + threadIdx.x;
    if (e >= E_) return;
    unsigned u1 = rb32(a0, a1, (unsigned)e);
    unsigned u2 = rb32(b0, b1, (unsigned)e);
    unsigned m1  = (u1 >= 0x80000000u) ? 1u : 0u;           // keep prob 0.5
    unsigned m12 = (m1 && u2 >= 0xC0000000u) ? 1u : 0u;     // joint keep
    g_cls[e] = (unsigned char)(m12 ? 0 : (m1 ? 1 : 2));
    int r = __ldg(rows + e);
    atomicAdd(&g_cnt[r], 1u + (m1 << 10) + (m12 << 20));
}

// ---- single-kernel scan: aggregates -> scanner-block prefix publish ----
// All NBLK=391 blocks are resident simultaneously (100K threads << chip), so
// the last block to arrive at the ticket scans ALL aggregates and publishes
// every block's exclusive prefix; other blocks spin on their own word only.
__global__ void k_scan() {
    __shared__ int s[SCAN_B];
    __shared__ unsigned s_base;
    __shared__ int s_scanner;
    int tid = threadIdx.x;
    int bid = blockIdx.x;
    int i = bid * SCAN_B + tid;
    unsigned pc = (i < N_) ? g_cnt[i] : 0u;
    int d = (int)(pc & 1023u);
    s[tid] = d;
    __syncthreads();
    for (int off = 1; off < SCAN_B; off <<= 1) {
        int v = s[tid];
        if (tid >= off) v += s[tid - off];
        __syncthreads();
        s[tid] = v;
        __syncthreads();
    }
    int total = s[SCAN_B - 1];

    if (tid == 0) {
        g_blocktot[bid] = total;
        __threadfence();
        s_scanner = (atomicAdd(&g_ticket2, 1) == NBLK - 1) ? 1 : 0;
    }
    __syncthreads();

    if (s_scanner) {
        // scan 391 aggregates (padded to 512, 2 per thread), publish prefixes
        __shared__ int t2[512];
        int a0 = (tid < NBLK) ? *((volatile int*)&g_blocktot[tid]) : 0;
        int a1 = (tid + 256 < NBLK) ? *((volatile int*)&g_blocktot[tid + 256]) : 0;
        t2[tid] = a0; t2[tid + 256] = a1;
        __syncthreads();
        for (int off = 1; off < 512; off <<= 1) {
            int u0 = t2[tid]       + ((tid >= off)       ? t2[tid - off]       : 0);
            int u1 = t2[tid + 256] + ((tid + 256 >= off) ? t2[tid + 256 - off] : 0);
            __syncthreads();
            t2[tid] = u0; t2[tid + 256] = u1;
            __syncthreads();
        }
        if (tid < NBLK)
            g_scanstate[tid] = (1u << 31) | (unsigned)(t2[tid] - a0);
        if (tid + 256 < NBLK)
            g_scanstate[tid + 256] = (1u << 31) | (unsigned)(t2[tid + 256] - a1);
        __threadfence();
        if (tid == 0) s_base = (unsigned)(t2[bid] - ((bid < 256) ? a0 : 0));
        // (scanner's own base: recompute safely below instead)
        __syncthreads();
        if (tid == 0) {
            unsigned st = g_scanstate[bid];
            s_base = st & 0x7FFFFFFFu;
        }
    } else if (tid == 0) {
        unsigned st;
        do { st = *((volatile unsigned*)&g_scanstate[bid]); } while (!(st >> 31));
        s_base = st & 0x7FFFFFFFu;
    }
    __syncthreads();

    if (i < N_) {
        unsigned rp = s_base + (unsigned)(s[tid] - d);
        unsigned cnt1  = (pc >> 10) & 1023u;
        unsigned cnt12 = (pc >> 20) & 1023u;
        g_rowseg[i] = make_uint2(rp, cnt12 | (cnt1 << 10) | ((unsigned)d << 20));
    }
}

// scatter edges into segmented CSR slots: [m12][m1-only][dropped]
__global__ void k_fill(const int* __restrict__ rows, const int* __restrict__ cols,
                       const float* __restrict__ vals) {
    int e = blockIdx.x * blockDim.x + threadIdx.x;
    if (e >= E_) return;
    int cls = (int)g_cls[e];

    int r = __ldg(rows + e);
    uint2 rs = __ldg(&g_rowseg[r]);
    unsigned old = atomicAdd(&g_cursor[r], 1u << (10 * cls));
    unsigned within = (old >> (10 * cls)) & 1023u;
    unsigned cnt12 = rs.y & 1023u;
    unsigned cnt1  = (rs.y >> 10) & 1023u;
    unsigned segbase = (cls == 0) ? 0u : ((cls == 1) ? cnt12 : cnt1);
    int pos = (int)(rs.x + segbase + within);
    g_edge[pos] = make_uint2((unsigned)__ldg(cols + e), __float_as_uint(__ldg(vals + e)));
}

// ---- gather SpMM passes: 1 warp per row, float2 per lane ----
// PASS 1: xin=embeds, out fst = sum - embeds[r]; order0 = sum v
// PASS 2: xin=fst (first cnt1), out emb1 = sum - (1+order0)*fst; num1, order1
// PASS 3: xin=emb1 (first cnt12), fused scoring + histogram; last block finds
//         the exact 16-bit top-1024 threshold from the 64K-bin histogram.
template<int PASS>
__global__ void k_pass(const float2* __restrict__ embeds, float* __restrict__ out,
                       unsigned n0, unsigned n1) {
    unsigned t = blockIdx.x * blockDim.x + threadIdx.x;
    int w = (int)(t >> 5);
    int c = (int)(t & 31u);

    if (w < N_) {
        const float2* xin = (PASS == 1) ? embeds : (PASS == 2 ? g_fst : g_emb1);
        const float* numin = (PASS == 2) ? g_order0 : g_num1;

        uint2 rs = __ldg(&g_rowseg[w]);
        int beg = (int)rs.x;
        int cnt = (PASS == 1) ? (int)((rs.y >> 20) & 1023u)
                : (PASS == 2) ? (int)((rs.y >> 10) & 1023u)
                              : (int)(rs.y & 1023u);

        float ax = 0.f, ay = 0.f;
        float ns = 0.f, o1acc = 0.f;

        #pragma unroll 4
        for (int e = beg; e < beg + cnt; ++e) {
            uint2 er = __ldg(&g_edge[e]);
            float v = __uint_as_float(er.y);
            float2 x = __ldg(&xin[(size_t)er.x * 32 + c]);
            ax += v * x.x; ay += v * x.y;
            if (PASS == 1) ns += v;
            else           ns += v * __ldg(&numin[er.x]);
            if (PASS == 2) o1acc += v;
        }

        size_t idx = (size_t)w * 32 + c;

        if (PASS == 1) {
            float2 b = __ldg(&embeds[idx]);
            g_fst[idx] = make_float2(ax - b.x, ay - b.y);
            if (c == 0) g_order0[w] = ns;
        } else if (PASS == 2) {
            float o = __ldg(&g_order0[w]);
            float f = 1.0f + o;
            float2 p = __ldg(&g_fst[idx]);
            g_emb1[idx] = make_float2(ax - f * p.x, ay - f * p.y);
            if (c == 0) { g_num1[w] = ns - 2.0f * o; g_order1[w] = o1acc; }
        } else {
            float o1  = __ldg(&g_order1[w]);
            float o0  = __ldg(&g_order0[w]);
            float n1v = __ldg(&g_num1[w]);
            float f = 1.0f + o1;
            float2 e1 = __ldg(&g_emb1[idx]);
            float2 p  = __ldg(&g_fst[idx]);
            float2 b  = __ldg(&embeds[idx]);
            float e2x = ax - f * e1.x, e2y = ay - f * e1.y;
            float num2 = ns - n1v - o1;
            float inv = 1.0f / (o0 + n1v + num2 + 1e-8f);
            float sx = (p.x + e1.x + e2x) * inv;
            float sy = (p.y + e1.y + e2y) * inv;
            float sa = sx * sx + sy * sy;
            float sb = b.x * b.x + b.y * b.y;
            float dp = sx * b.x + sy * b.y;
            for (int off = 16; off > 0; off >>= 1) {
                sa += __shfl_down_sync(0xFFFFFFFFu, sa, off);
                sb += __shfl_down_sync(0xFFFFFFFFu, sb, off);
                dp += __shfl_down_sync(0xFFFFFFFFu, dp, off);
            }
            if (c == 0) {
                float na = sqrtf(sa); if (na < 1e-12f) na = 1e-12f;
                float nb = sqrtf(sb); if (nb < 1e-12f) nb = 1e-12f;
                float score = dp / (na * nb);
                unsigned bits = rb32(n0, n1, (unsigned)w);
                float u = __uint_as_float(0x3F800000u | (bits >> 9)) - 1.0f;
                score += -logf(-logf(u));
                out[w] = score;
                unsigned kk = __float_as_uint(score);
                kk = (kk & 0x80000000u) ? ~kk : (kk | 0x80000000u);
                g_keys[w] = kk;
                atomicAdd(&g_hist64[kk >> 16], 1u);
            }
        }
    }

    // ---- PASS 3 only: last-block threshold finder ----
    if (PASS == 3) {
        __shared__ int s_last;
        int tid = threadIdx.x;
        __threadfence();
        __syncthreads();
        if (tid == 0)
            s_last = (atomicAdd(&g_ticket3, 1) == (int)gridDim.x - 1) ? 1 : 0;
        __syncthreads();
        if (!s_last) return;

        // 256 threads: superbin sums (256 superbins x 256 bins), coalesced per warp
        __shared__ unsigned sup[256 + 1];
        __shared__ unsigned bins[256 + 1];
        __shared__ int s_star;
        int wid = tid >> 5, lane = tid & 31;
        for (int sb = wid; sb < 256; sb += 8) {
            unsigned acc = 0u;
            #pragma unroll
            for (int j = 0; j < 8; j++)
                acc += *((volatile unsigned*)&g_hist64[sb * 256 + lane + 32 * j]);
            for (int off = 16; off > 0; off >>= 1)
                acc += __shfl_down_sync(0xFFFFFFFFu, acc, off);
            if (lane == 0) sup[sb] = acc;
        }
        if (tid == 0) sup[256] = 0u;
        __syncthreads();
        // inclusive suffix sum over superbins
        for (int off = 1; off < 256; off <<= 1) {
            unsigned v = sup[tid] + ((tid + off < 256) ? sup[tid + off] : 0u);
            __syncthreads();
            sup[tid] = v;
            __syncthreads();
        }
        {
            unsigned here = sup[tid];
            unsigned next = (tid < 255) ? sup[tid + 1] : 0u;
            if (here >= NCAND && next < NCAND) s_star = tid;
        }
        __syncthreads();
        int ss = s_star;
        unsigned above = (ss < 255) ? sup[ss + 1] : 0u;   // count strictly above superbin
        bins[tid] = *((volatile unsigned*)&g_hist64[ss * 256 + tid]);
        __syncthreads();
        // inclusive suffix sum over the 256 bins of superbin ss
        for (int off = 1; off < 256; off <<= 1) {
            unsigned v = bins[tid] + ((tid + off < 256) ? bins[tid + off] : 0u);
            __syncthreads();
            bins[tid] = v;
            __syncthreads();
        }
        {
            unsigned here = above + bins[tid];
            unsigned next = above + ((tid < 255) ? bins[tid + 1] : 0u);
            if (here >= NCAND && next < NCAND)
                g_prefix = ((unsigned)(ss * 256 + tid)) << 16;
        }
    }
}

// ---- fused select + sort: grid selects candidates; last block bitonic-sorts ----
__global__ void k_selsort(float* __restrict__ out) {
    __shared__ unsigned long long sm[CAP];
    __shared__ int s_last;
    int tid = threadIdx.x;
    unsigned pref = g_prefix;                  // 16-bit threshold prefix (low bits 0)

    int i = blockIdx.x * blockDim.x + tid;
    if (i < N_) {
        unsigned k = g_keys[i];
        if (k >= pref) {
            int p = atomicAdd(&g_selcount, 1);
            if (p < CAP)
                g_cand[p] = (((unsigned long long)k) << 32) | (unsigned)(~(unsigned)i);
        }
    }
    __threadfence();
    __syncthreads();
    if (tid == 0)
        s_last = (atomicAdd(&g_ticket, 1) == (int)gridDim.x - 1) ? 1 : 0;
    __syncthreads();
    if (!s_last) return;

    int cnt = *((volatile int*)&g_selcount); if (cnt > CAP) cnt = CAP;
    for (int s = 0; s < CAP / 1024; s++) {
        int j = tid + s * 1024;
        sm[j] = (j < cnt) ? *((volatile unsigned long long*)&g_cand[j]) : 0ull;
    }
    __syncthreads();
    for (int k = 2; k <= CAP; k <<= 1) {
        for (int j = k >> 1; j > 0; j >>= 1) {
            for (int s = 0; s < CAP / 1024; s++) {
                int a = tid + s * 1024;
                int l = a ^ j;
                if (l > a) {
                    unsigned long long va = sm[a], vb = sm[l];
                    bool up = ((a & k) == 0);
                    if ((va < vb) == up) { sm[a] = vb; sm[l] = va; }
                }
            }
            __syncthreads();
        }
    }
    unsigned idx = ~((unsigned)sm[tid]);
    out[N_ + tid] = (float)idx;
}

// ---------------- launch --------------------------------------------------------
extern "C" void kernel_launch(void* const* d_in, const int* in_sizes, int n_in,
                              void* d_out, int out_size) {
    const int*   rows   = (const int*)d_in[0];
    const int*   cols   = (const int*)d_in[1];
    const float* vals   = (const float*)d_in[2];
    const float* embeds = (const float*)d_in[3];
    float* out = (float*)d_out;

    // key chain (partitionable): key(42) -> (split) kd1 -> (split) kd2 -> (split) kn
    unsigned k0 = 0u, k1 = 42u, nk[2], kd1[2], kd2[2], kn[2];
    jax_split_part(k0, k1, nk, kd1); k0 = nk[0]; k1 = nk[1];
    jax_split_part(k0, k1, nk, kd2); k0 = nk[0]; k1 = nk[1];
    jax_split_part(k0, k1, nk, kn);

    const int B = 256;
    const int gN   = (N_ + B - 1) / B;
    const int gN32 = (N_ * 32 + B - 1) / B;
    const int gE   = (E_ + B - 1) / B;
    const int gS   = (N_ + 1023) / 1024;

    k_zero<<<gN, B>>>();
    k_count<<<gE, B>>>(rows, kd1[0], kd1[1], kd2[0], kd2[1]);
    k_scan<<<NBLK, SCAN_B>>>();
    k_fill<<<gE, B>>>(rows, cols, vals);      // <- profiled launch (index 3)

    k_pass<1><<<gN32, B>>>((const float2*)embeds, out, kn[0], kn[1]);
    k_pass<2><<<gN32, B>>>((const float2*)embeds, out, kn[0], kn[1]);
    k_pass<3><<<gN32, B>>>((const float2*)embeds, out, kn[0], kn[1]);

    k_selsort<<<gS, 1024>>>(out);
}

// round 10
// speedup vs baseline: 1.1092x; 1.0691x over previous
#include <cuda_runtime.h>
#include <cstdint>

#define N_ 100000
#define E_ 3200000
#define NCAND 1024
#define CAP 4096
#define SCAN_B 256
#define NBLK ((N_ + SCAN_B - 1) / SCAN_B)   // 391

// ---------------- device scratch (static, no runtime allocation) ----------------
__device__ float2 g_fst [N_*32];
__device__ float2 g_emb1[N_*32];
__device__ uint2  g_edge[E_];          // CSR records: (col, val bits), segmented
__device__ unsigned short g_rank[E_];  // within-segment rank | cls<<12
__device__ float  g_order0[N_];
__device__ float  g_order1[N_];
__device__ float  g_num1[N_];
__device__ unsigned g_cnt[N_];         // packed: deg | cnt_m1<<10 | cnt_m12<<20
__device__ uint2  g_rowseg[N_];        // .x = rowptr, .y = cnt12 | cnt1<<10 | deg<<20
__device__ int    g_blocktot[NBLK];
__device__ int    g_blockoff[NBLK];
__device__ unsigned g_keys[N_];
__device__ unsigned g_hist64[65536];
__device__ unsigned g_prefix;
__device__ int g_ticket;
__device__ int g_ticket2;
__device__ int g_selcount;
__device__ unsigned long long g_cand[CAP];

// ---------------- Threefry-2x32 (20 rounds, 5 key injections) -------------------
#define TFR(a,b,r) { a += b; b = ((b << (r)) | (b >> (32-(r)))); b ^= a; }

__host__ __device__ __forceinline__ void tf2x32(unsigned k0, unsigned k1,
                                                unsigned& x0, unsigned& x1) {
    unsigned k2 = k0 ^ k1 ^ 0x1BD11BDAu;
    x0 += k0; x1 += k1;
    TFR(x0,x1,13) TFR(x0,x1,15) TFR(x0,x1,26) TFR(x0,x1,6)
    x0 += k1; x1 += k2 + 1u;
    TFR(x0,x1,17) TFR(x0,x1,29) TFR(x0,x1,16) TFR(x0,x1,24)
    x0 += k2; x1 += k0 + 2u;
    TFR(x0,x1,13) TFR(x0,x1,15) TFR(x0,x1,26) TFR(x0,x1,6)
    x0 += k0; x1 += k1 + 3u;
    TFR(x0,x1,17) TFR(x0,x1,29) TFR(x0,x1,16) TFR(x0,x1,24)
    x0 += k1; x1 += k2 + 4u;
    TFR(x0,x1,13) TFR(x0,x1,15) TFR(x0,x1,26) TFR(x0,x1,6)
    x0 += k2; x1 += k0 + 5u;
}

static void jax_split_part(unsigned k0, unsigned k1, unsigned* nk, unsigned* sk) {
    unsigned a0 = 0u, a1 = 0u; tf2x32(k0, k1, a0, a1);
    unsigned b0 = 0u, b1 = 1u; tf2x32(k0, k1, b0, b1);
    nk[0] = a0; nk[1] = a1;
    sk[0] = b0; sk[1] = b1;
}

__device__ __forceinline__ unsigned rb32(unsigned k0, unsigned k1, unsigned i) {
    unsigned x0 = 0u, x1 = i;
    tf2x32(k0, k1, x0, x1);
    return x0 ^ x1;
}

// ---------------- kernels -------------------------------------------------------

__global__ void k_zero() {
    int i = blockIdx.x * blockDim.x + threadIdx.x;
    if (i < N_) g_cnt[i] = 0u;
    if (i < 65536) g_hist64[i] = 0u;
    if (i == 0) {
        g_prefix = 0u; g_selcount = 0; g_ticket = 0; g_ticket2 = 0;
    }
}

// RNG masks + packed per-row class counts; the atomic's return value yields the
// edge's within-segment rank, eliminating k_fill's cursor atomic entirely.
__global__ void k_count(const int* __restrict__ rows,
                        unsigned a0, unsigned a1, unsigned b0, unsigned b1) {
    int e = blockIdx.x * blockDim.x + threadIdx.x;
    if (e >= E_) return;
    unsigned u1 = rb32(a0, a1, (unsigned)e);
    unsigned u2 = rb32(b0, b1, (unsigned)e);
    unsigned m1  = (u1 >= 0x80000000u) ? 1u : 0u;           // keep prob 0.5
    unsigned m12 = (m1 && u2 >= 0xC0000000u) ? 1u : 0u;     // joint keep
    int r = __ldg(rows + e);
    unsigned old = atomicAdd(&g_cnt[r], 1u + (m1 << 10) + (m12 << 20));
    unsigned d0   = old & 1023u;
    unsigned dm1  = (old >> 10) & 1023u;
    unsigned dm12 = (old >> 20) & 1023u;
    unsigned cls  = m12 ? 0u : (m1 ? 1u : 2u);
    unsigned rank = m12 ? dm12 : (m1 ? (dm1 - dm12) : (d0 - dm1));
    g_rank[e] = (unsigned short)(rank | (cls << 12));
}

// ---- fused block reduce + inter-block scan (last-block ticket) ----
__global__ void k_scanA() {
    __shared__ int s[SCAN_B];
    __shared__ int s_last;
    int tid = threadIdx.x;
    int i = blockIdx.x * SCAN_B + tid;
    s[tid] = (i < N_) ? (int)(g_cnt[i] & 1023u) : 0;
    __syncthreads();
    for (int off = SCAN_B / 2; off > 0; off >>= 1) {
        if (tid < off) s[tid] += s[tid + off];
        __syncthreads();
    }
    if (tid == 0) g_blocktot[blockIdx.x] = s[0];
    __threadfence();
    __syncthreads();
    if (tid == 0)
        s_last = (atomicAdd(&g_ticket2, 1) == NBLK - 1) ? 1 : 0;
    __syncthreads();
    if (!s_last) return;

    // last block: exclusive scan of 391 block totals (padded to 512, 2/thread)
    __shared__ int t2[512];
    int a0 = (tid < NBLK) ? *((volatile int*)&g_blocktot[tid]) : 0;
    int a1 = (tid + 256 < NBLK) ? *((volatile int*)&g_blocktot[tid + 256]) : 0;
    t2[tid] = a0; t2[tid + 256] = a1;
    __syncthreads();
    for (int off = 1; off < 512; off <<= 1) {
        int u0 = t2[tid]       + ((tid >= off)       ? t2[tid - off]       : 0);
        int u1 = t2[tid + 256] + ((tid + 256 >= off) ? t2[tid + 256 - off] : 0);
        __syncthreads();
        t2[tid] = u0; t2[tid + 256] = u1;
        __syncthreads();
    }
    if (tid < NBLK)       g_blockoff[tid]       = t2[tid] - a0;
    if (tid + 256 < NBLK) g_blockoff[tid + 256] = t2[tid + 256] - a1;
}

__global__ void k_scanC() {
    __shared__ int s[SCAN_B];
    int tid = threadIdx.x;
    int i = blockIdx.x * SCAN_B + tid;
    unsigned pc = (i < N_) ? g_cnt[i] : 0u;
    int d = (int)(pc & 1023u);
    s[tid] = d;
    __syncthreads();
    for (int off = 1; off < SCAN_B; off <<= 1) {
        int v = s[tid];
        if (tid >= off) v += s[tid - off];
        __syncthreads();
        s[tid] = v;
        __syncthreads();
    }
    if (i < N_) {
        unsigned rp = (unsigned)(g_blockoff[blockIdx.x] + s[tid] - d);
        unsigned cnt1  = (pc >> 10) & 1023u;
        unsigned cnt12 = (pc >> 20) & 1023u;
        g_rowseg[i] = make_uint2(rp, cnt12 | (cnt1 << 10) | ((unsigned)d << 20));
    }
}

// scatter edges into segmented CSR slots: [m12][m1-only][dropped] — atomic-free
__global__ void k_fill(const int* __restrict__ rows, const int* __restrict__ cols,
                       const float* __restrict__ vals) {
    int e = blockIdx.x * blockDim.x + threadIdx.x;
    if (e >= E_) return;
    unsigned rk = g_rank[e];
    unsigned cls = rk >> 12;
    unsigned within = rk & 0xFFFu;

    int r = __ldg(rows + e);
    uint2 rs = __ldg(&g_rowseg[r]);
    unsigned cnt12 = rs.y & 1023u;
    unsigned cnt1  = (rs.y >> 10) & 1023u;
    unsigned segbase = (cls == 0u) ? 0u : ((cls == 1u) ? cnt12 : cnt1);
    int pos = (int)(rs.x + segbase + within);
    g_edge[pos] = make_uint2((unsigned)__ldg(cols + e), __float_as_uint(__ldg(vals + e)));
}

// ---- gather SpMM passes: 1 warp per row, float2 per lane ----
template<int PASS>
__global__ void k_pass(const float2* __restrict__ embeds, float* __restrict__ out,
                       unsigned n0, unsigned n1) {
    unsigned t = blockIdx.x * blockDim.x + threadIdx.x;
    int w = (int)(t >> 5);
    int c = (int)(t & 31u);
    if (w >= N_) return;

    const float2* xin = (PASS == 1) ? embeds : (PASS == 2 ? g_fst : g_emb1);
    const float* numin = (PASS == 2) ? g_order0 : g_num1;

    uint2 rs = __ldg(&g_rowseg[w]);
    int beg = (int)rs.x;
    int cnt = (PASS == 1) ? (int)((rs.y >> 20) & 1023u)
            : (PASS == 2) ? (int)((rs.y >> 10) & 1023u)
                          : (int)(rs.y & 1023u);

    float ax = 0.f, ay = 0.f;
    float ns = 0.f, o1acc = 0.f;

    #pragma unroll 4
    for (int e = beg; e < beg + cnt; ++e) {
        uint2 er = __ldg(&g_edge[e]);
        float v = __uint_as_float(er.y);
        float2 x = __ldg(&xin[(size_t)er.x * 32 + c]);
        ax += v * x.x; ay += v * x.y;
        if (PASS == 1) ns += v;
        else           ns += v * __ldg(&numin[er.x]);
        if (PASS == 2) o1acc += v;
    }

    size_t idx = (size_t)w * 32 + c;

    if (PASS == 1) {
        float2 b = __ldg(&embeds[idx]);
        g_fst[idx] = make_float2(ax - b.x, ay - b.y);
        if (c == 0) g_order0[w] = ns;
    } else if (PASS == 2) {
        float o = __ldg(&g_order0[w]);
        float f = 1.0f + o;
        float2 p = __ldg(&g_fst[idx]);
        g_emb1[idx] = make_float2(ax - f * p.x, ay - f * p.y);
        if (c == 0) { g_num1[w] = ns - 2.0f * o; g_order1[w] = o1acc; }
    } else {
        float o1  = __ldg(&g_order1[w]);
        float o0  = __ldg(&g_order0[w]);
        float n1v = __ldg(&g_num1[w]);
        float f = 1.0f + o1;
        float2 e1 = __ldg(&g_emb1[idx]);
        float2 p  = __ldg(&g_fst[idx]);
        float2 b  = __ldg(&embeds[idx]);
        float e2x = ax - f * e1.x, e2y = ay - f * e1.y;
        float num2 = ns - n1v - o1;
        float inv = 1.0f / (o0 + n1v + num2 + 1e-8f);
        float sx = (p.x + e1.x + e2x) * inv;
        float sy = (p.y + e1.y + e2y) * inv;
        float sa = sx * sx + sy * sy;
        float sb = b.x * b.x + b.y * b.y;
        float dp = sx * b.x + sy * b.y;
        for (int off = 16; off > 0; off >>= 1) {
            sa += __shfl_down_sync(0xFFFFFFFFu, sa, off);
            sb += __shfl_down_sync(0xFFFFFFFFu, sb, off);
            dp += __shfl_down_sync(0xFFFFFFFFu, dp, off);
        }
        if (c == 0) {
            float na = sqrtf(sa); if (na < 1e-12f) na = 1e-12f;
            float nb = sqrtf(sb); if (nb < 1e-12f) nb = 1e-12f;
            float score = dp / (na * nb);
            unsigned bits = rb32(n0, n1, (unsigned)w);
            float u = __uint_as_float(0x3F800000u | (bits >> 9)) - 1.0f;
            score += -logf(-logf(u));
            out[w] = score;
            unsigned kk = __float_as_uint(score);
            kk = (kk & 0x80000000u) ? ~kk : (kk | 0x80000000u);
            g_keys[w] = kk;
            atomicAdd(&g_hist64[kk >> 16], 1u);
        }
    }
}

// ---- single-block threshold finder over the 64K-bin histogram ----
__global__ void k_thresh() {
    __shared__ unsigned sup[1024];
    int t = threadIdx.x;
    sup[t] = 0u;
    __syncthreads();
    for (int j = 0; j < 64; j++) {
        int b = j * 1024 + t;
        unsigned h = g_hist64[b];
        if (h) atomicAdd(&sup[b >> 6], h);
    }
    __syncthreads();
    for (int off = 1; off < 1024; off <<= 1) {
        unsigned v = sup[t] + ((t + off < 1024) ? sup[t + off] : 0u);
        __syncthreads();
        sup[t] = v;
        __syncthreads();
    }
    unsigned sufHere = sup[t];
    unsigned sufNext = (t < 1023) ? sup[t + 1] : 0u;
    if (sufHere >= NCAND && sufNext < NCAND) {
        unsigned acc = sufNext;
        int T = t * 64;
        for (int b = 63; b >= 0; --b) {
            acc += g_hist64[t * 64 + b];
            if (acc >= NCAND) { T = t * 64 + b; break; }
        }
        g_prefix = ((unsigned)T) << 16;
    }
}

// ---- fused select + sort: grid selects candidates; last block bitonic-sorts ----
__global__ void k_selsort(float* __restrict__ out) {
    __shared__ unsigned long long sm[CAP];
    __shared__ int s_last;
    int tid = threadIdx.x;
    unsigned pref = g_prefix;

    int i = blockIdx.x * blockDim.x + tid;
    if (i < N_) {
        unsigned k = g_keys[i];
        if (k >= pref) {
            int p = atomicAdd(&g_selcount, 1);
            if (p < CAP)
                g_cand[p] = (((unsigned long long)k) << 32) | (unsigned)(~(unsigned)i);
        }
    }
    __threadfence();
    __syncthreads();
    if (tid == 0)
        s_last = (atomicAdd(&g_ticket, 1) == (int)gridDim.x - 1) ? 1 : 0;
    __syncthreads();
    if (!s_last) return;

    int cnt = *((volatile int*)&g_selcount); if (cnt > CAP) cnt = CAP;
    for (int s = 0; s < CAP / 1024; s++) {
        int j = tid + s * 1024;
        sm[j] = (j < cnt) ? *((volatile unsigned long long*)&g_cand[j]) : 0ull;
    }
    __syncthreads();
    for (int k = 2; k <= CAP; k <<= 1) {
        for (int j = k >> 1; j > 0; j >>= 1) {
            for (int s = 0; s < CAP / 1024; s++) {
                int a = tid + s * 1024;
                int l = a ^ j;
                if (l > a) {
                    unsigned long long va = sm[a], vb = sm[l];
                    bool up = ((a & k) == 0);
                    if ((va < vb) == up) { sm[a] = vb; sm[l] = va; }
                }
            }
            __syncthreads();
        }
    }
    unsigned idx = ~((unsigned)sm[tid]);
    out[N_ + tid] = (float)idx;
}

// ---------------- launch --------------------------------------------------------
extern "C" void kernel_launch(void* const* d_in, const int* in_sizes, int n_in,
                              void* d_out, int out_size) {
    const int*   rows   = (const int*)d_in[0];
    const int*   cols   = (const int*)d_in[1];
    const float* vals   = (const float*)d_in[2];
    const float* embeds = (const float*)d_in[3];
    float* out = (float*)d_out;

    // key chain (partitionable): key(42) -> (split) kd1 -> (split) kd2 -> (split) kn
    unsigned k0 = 0u, k1 = 42u, nk[2], kd1[2], kd2[2], kn[2];
    jax_split_part(k0, k1, nk, kd1); k0 = nk[0]; k1 = nk[1];
    jax_split_part(k0, k1, nk, kd2); k0 = nk[0]; k1 = nk[1];
    jax_split_part(k0, k1, nk, kn);

    const int B = 256;
    const int gN   = (N_ + B - 1) / B;
    const int gN32 = (N_ * 32 + B - 1) / B;
    const int gE   = (E_ + B - 1) / B;
    const int gS   = (N_ + 1023) / 1024;

    k_zero<<<gN, B>>>();
    k_count<<<gE, B>>>(rows, kd1[0], kd1[1], kd2[0], kd2[1]);
    k_scanA<<<NBLK, SCAN_B>>>();
    k_scanC<<<NBLK, SCAN_B>>>();
    k_fill<<<gE, B>>>(rows, cols, vals);      // atomic-free placement

    k_pass<1><<<gN32, B>>>((const float2*)embeds, out, kn[0], kn[1]);
    k_pass<2><<<gN32, B>>>((const float2*)embeds, out, kn[0], kn[1]);
    k_pass<3><<<gN32, B>>>((const float2*)embeds, out, kn[0], kn[1]);

    k_thresh<<<1, 1024>>>();
    k_selsort<<<gS, 1024>>>(out);
}

// round 11
// speedup vs baseline: 1.1847x; 1.0681x over previous
#include <cuda_runtime.h>
#include <cstdint>

#define N_ 100000
#define E_ 3200000
#define NCAND 1024
#define CAP 2048
#define SCAN_B 256
#define NBLK ((N_ + SCAN_B - 1) / SCAN_B)   // 391

// ---------------- device scratch (static, zero-init; self-cleaning) -------------
__device__ float2 g_fst [N_*32];
__device__ float2 g_emb1[N_*32];
__device__ uint2  g_edge[E_];          // CSR records: (col, val bits), segmented
__device__ unsigned short g_rank[E_];  // within-segment rank | cls<<12
__device__ float  g_order0[N_];
__device__ float  g_order1[N_];
__device__ float  g_num1[N_];
__device__ unsigned g_cnt[N_];         // packed: deg | cnt_m1<<10 | cnt_m12<<20 (zeroed by scanC)
__device__ uint2  g_rowseg[N_];        // .x = rowptr, .y = cnt12 | cnt1<<10 | deg<<20
__device__ int    g_blocktot[NBLK];
__device__ int    g_blockoff[NBLK];
__device__ unsigned g_keys[N_];
__device__ unsigned g_hist64[65536];   // zeroed by thresh after use
__device__ unsigned g_prefix;
__device__ int g_ticket;               // reset by selsort last block
__device__ int g_ticket2;              // reset by scanA scanner block
__device__ int g_selcount;             // reset by selsort last block
__device__ unsigned long long g_cand[CAP];

// ---------------- Threefry-2x32 (20 rounds, 5 key injections) -------------------
#define TFR(a,b,r) { a += b; b = ((b << (r)) | (b >> (32-(r)))); b ^= a; }

__host__ __device__ __forceinline__ void tf2x32(unsigned k0, unsigned k1,
                                                unsigned& x0, unsigned& x1) {
    unsigned k2 = k0 ^ k1 ^ 0x1BD11BDAu;
    x0 += k0; x1 += k1;
    TFR(x0,x1,13) TFR(x0,x1,15) TFR(x0,x1,26) TFR(x0,x1,6)
    x0 += k1; x1 += k2 + 1u;
    TFR(x0,x1,17) TFR(x0,x1,29) TFR(x0,x1,16) TFR(x0,x1,24)
    x0 += k2; x1 += k0 + 2u;
    TFR(x0,x1,13) TFR(x0,x1,15) TFR(x0,x1,26) TFR(x0,x1,6)
    x0 += k0; x1 += k1 + 3u;
    TFR(x0,x1,17) TFR(x0,x1,29) TFR(x0,x1,16) TFR(x0,x1,24)
    x0 += k1; x1 += k2 + 4u;
    TFR(x0,x1,13) TFR(x0,x1,15) TFR(x0,x1,26) TFR(x0,x1,6)
    x0 += k2; x1 += k0 + 5u;
}

static void jax_split_part(unsigned k0, unsigned k1, unsigned* nk, unsigned* sk) {
    unsigned a0 = 0u, a1 = 0u; tf2x32(k0, k1, a0, a1);
    unsigned b0 = 0u, b1 = 1u; tf2x32(k0, k1, b0, b1);
    nk[0] = a0; nk[1] = a1;
    sk[0] = b0; sk[1] = b1;
}

__device__ __forceinline__ unsigned rb32(unsigned k0, unsigned k1, unsigned i) {
    unsigned x0 = 0u, x1 = i;
    tf2x32(k0, k1, x0, x1);
    return x0 ^ x1;
}

// ---------------- kernels -------------------------------------------------------

// RNG masks + packed per-row class counts; the atomic's return value yields the
// edge's within-segment rank. Requires g_cnt == 0 on entry (scanC restores it).
__global__ void k_count(const int* __restrict__ rows,
                        unsigned a0, unsigned a1, unsigned b0, unsigned b1) {
    int e = blockIdx.x * blockDim.x + threadIdx.x;
    if (e >= E_) return;
    unsigned u1 = rb32(a0, a1, (unsigned)e);
    unsigned u2 = rb32(b0, b1, (unsigned)e);
    unsigned m1  = (u1 >= 0x80000000u) ? 1u : 0u;           // keep prob 0.5
    unsigned m12 = (m1 && u2 >= 0xC0000000u) ? 1u : 0u;     // joint keep
    int r = __ldg(rows + e);
    unsigned old = atomicAdd(&g_cnt[r], 1u + (m1 << 10) + (m12 << 20));
    unsigned d0   = old & 1023u;
    unsigned dm1  = (old >> 10) & 1023u;
    unsigned dm12 = (old >> 20) & 1023u;
    unsigned cls  = m12 ? 0u : (m1 ? 1u : 2u);
    unsigned rank = m12 ? dm12 : (m1 ? (dm1 - dm12) : (d0 - dm1));
    g_rank[e] = (unsigned short)(rank | (cls << 12));
}

// ---- fused block reduce + inter-block scan (last-block ticket) ----
__global__ void k_scanA() {
    __shared__ int s[SCAN_B];
    __shared__ int s_last;
    int tid = threadIdx.x;
    int i = blockIdx.x * SCAN_B + tid;
    s[tid] = (i < N_) ? (int)(g_cnt[i] & 1023u) : 0;
    __syncthreads();
    for (int off = SCAN_B / 2; off > 0; off >>= 1) {
        if (tid < off) s[tid] += s[tid + off];
        __syncthreads();
    }
    if (tid == 0) g_blocktot[blockIdx.x] = s[0];
    __threadfence();
    __syncthreads();
    if (tid == 0)
        s_last = (atomicAdd(&g_ticket2, 1) == NBLK - 1) ? 1 : 0;
    __syncthreads();
    if (!s_last) return;

    if (tid == 0) g_ticket2 = 0;   // self-clean for next replay

    // last block: exclusive scan of 391 block totals (padded to 512, 2/thread)
    __shared__ int t2[512];
    int a0 = (tid < NBLK) ? *((volatile int*)&g_blocktot[tid]) : 0;
    int a1 = (tid + 256 < NBLK) ? *((volatile int*)&g_blocktot[tid + 256]) : 0;
    t2[tid] = a0; t2[tid + 256] = a1;
    __syncthreads();
    for (int off = 1; off < 512; off <<= 1) {
        int u0 = t2[tid]       + ((tid >= off)       ? t2[tid - off]       : 0);
        int u1 = t2[tid + 256] + ((tid + 256 >= off) ? t2[tid + 256 - off] : 0);
        __syncthreads();
        t2[tid] = u0; t2[tid + 256] = u1;
        __syncthreads();
    }
    if (tid < NBLK)       g_blockoff[tid]       = t2[tid] - a0;
    if (tid + 256 < NBLK) g_blockoff[tid + 256] = t2[tid + 256] - a1;
}

__global__ void k_scanC() {
    __shared__ int s[SCAN_B];
    int tid = threadIdx.x;
    int i = blockIdx.x * SCAN_B + tid;
    unsigned pc = (i < N_) ? g_cnt[i] : 0u;
    int d = (int)(pc & 1023u);
    s[tid] = d;
    __syncthreads();
    for (int off = 1; off < SCAN_B; off <<= 1) {
        int v = s[tid];
        if (tid >= off) v += s[tid - off];
        __syncthreads();
        s[tid] = v;
        __syncthreads();
    }
    if (i < N_) {
        unsigned rp = (unsigned)(g_blockoff[blockIdx.x] + s[tid] - d);
        unsigned cnt1  = (pc >> 10) & 1023u;
        unsigned cnt12 = (pc >> 20) & 1023u;
        g_rowseg[i] = make_uint2(rp, cnt12 | (cnt1 << 10) | ((unsigned)d << 20));
        g_cnt[i] = 0u;                 // self-clean for next replay
    }
}

// scatter edges into segmented CSR slots: [m12][m1-only][dropped] — atomic-free,
// 2 edges per thread with vectorized input loads.
__global__ void k_fill(const int* __restrict__ rows, const int* __restrict__ cols,
                       const float* __restrict__ vals) {
    int p = blockIdx.x * blockDim.x + threadIdx.x;
    if (p >= E_ / 2) return;
    int2   rr = __ldg((const int2*)rows + p);
    int2   cc = __ldg((const int2*)cols + p);
    float2 vv = __ldg((const float2*)vals + p);
    unsigned rk2 = __ldg((const unsigned*)g_rank + p);

    {
        unsigned rk = rk2 & 0xFFFFu;
        unsigned cls = rk >> 12, within = rk & 0xFFFu;
        uint2 rs = __ldg(&g_rowseg[rr.x]);
        unsigned cnt12 = rs.y & 1023u, cnt1 = (rs.y >> 10) & 1023u;
        unsigned segbase = (cls == 0u) ? 0u : ((cls == 1u) ? cnt12 : cnt1);
        g_edge[rs.x + segbase + within] =
            make_uint2((unsigned)cc.x, __float_as_uint(vv.x));
    }
    {
        unsigned rk = rk2 >> 16;
        unsigned cls = rk >> 12, within = rk & 0xFFFu;
        uint2 rs = __ldg(&g_rowseg[rr.y]);
        unsigned cnt12 = rs.y & 1023u, cnt1 = (rs.y >> 10) & 1023u;
        unsigned segbase = (cls == 0u) ? 0u : ((cls == 1u) ? cnt12 : cnt1);
        g_edge[rs.x + segbase + within] =
            make_uint2((unsigned)cc.y, __float_as_uint(vv.y));
    }
}

// ---- gather SpMM passes: 1 warp per row, float2 per lane ----
template<int PASS>
__global__ void k_pass(const float2* __restrict__ embeds, float* __restrict__ out,
                       unsigned n0, unsigned n1) {
    unsigned t = blockIdx.x * blockDim.x + threadIdx.x;
    int w = (int)(t >> 5);
    int c = (int)(t & 31u);
    if (w >= N_) return;

    const float2* xin = (PASS == 1) ? embeds : (PASS == 2 ? g_fst : g_emb1);
    const float* numin = (PASS == 2) ? g_order0 : g_num1;

    uint2 rs = __ldg(&g_rowseg[w]);
    int beg = (int)rs.x;
    int cnt = (PASS == 1) ? (int)((rs.y >> 20) & 1023u)
            : (PASS == 2) ? (int)((rs.y >> 10) & 1023u)
                          : (int)(rs.y & 1023u);

    float ax = 0.f, ay = 0.f;
    float ns = 0.f, o1acc = 0.f;

    #pragma unroll 4
    for (int e = beg; e < beg + cnt; ++e) {
        uint2 er = __ldg(&g_edge[e]);
        float v = __uint_as_float(er.y);
        float2 x = __ldg(&xin[(size_t)er.x * 32 + c]);
        ax += v * x.x; ay += v * x.y;
        if (PASS == 1) ns += v;
        else           ns += v * __ldg(&numin[er.x]);
        if (PASS == 2) o1acc += v;
    }

    size_t idx = (size_t)w * 32 + c;

    if (PASS == 1) {
        float2 b = __ldg(&embeds[idx]);
        g_fst[idx] = make_float2(ax - b.x, ay - b.y);
        if (c == 0) g_order0[w] = ns;
    } else if (PASS == 2) {
        float o = __ldg(&g_order0[w]);
        float f = 1.0f + o;
        float2 p = __ldg(&g_fst[idx]);
        g_emb1[idx] = make_float2(ax - f * p.x, ay - f * p.y);
        if (c == 0) { g_num1[w] = ns - 2.0f * o; g_order1[w] = o1acc; }
    } else {
        float o1  = __ldg(&g_order1[w]);
        float o0  = __ldg(&g_order0[w]);
        float n1v = __ldg(&g_num1[w]);
        float f = 1.0f + o1;
        float2 e1 = __ldg(&g_emb1[idx]);
        float2 p  = __ldg(&g_fst[idx]);
        float2 b  = __ldg(&embeds[idx]);
        float e2x = ax - f * e1.x, e2y = ay - f * e1.y;
        float num2 = ns - n1v - o1;
        float inv = 1.0f / (o0 + n1v + num2 + 1e-8f);
        float sx = (p.x + e1.x + e2x) * inv;
        float sy = (p.y + e1.y + e2y) * inv;
        float sa = sx * sx + sy * sy;
        float sb = b.x * b.x + b.y * b.y;
        float dp = sx * b.x + sy * b.y;
        for (int off = 16; off > 0; off >>= 1) {
            sa += __shfl_down_sync(0xFFFFFFFFu, sa, off);
            sb += __shfl_down_sync(0xFFFFFFFFu, sb, off);
            dp += __shfl_down_sync(0xFFFFFFFFu, dp, off);
        }
        if (c == 0) {
            float na = sqrtf(sa); if (na < 1e-12f) na = 1e-12f;
            float nb = sqrtf(sb); if (nb < 1e-12f) nb = 1e-12f;
            float score = dp / (na * nb);
            unsigned bits = rb32(n0, n1, (unsigned)w);
            float u = __uint_as_float(0x3F800000u | (bits >> 9)) - 1.0f;
            score += -logf(-logf(u));
            out[w] = score;
            unsigned kk = __float_as_uint(score);
            kk = (kk & 0x80000000u) ? ~kk : (kk | 0x80000000u);
            g_keys[w] = kk;
            atomicAdd(&g_hist64[kk >> 16], 1u);
        }
    }
}

// ---- single-block threshold finder; zeroes g_hist64 afterward (self-clean) ----
__global__ void k_thresh() {
    __shared__ unsigned sup[1024];
    int t = threadIdx.x;
    sup[t] = 0u;
    __syncthreads();
    for (int j = 0; j < 64; j++) {
        int b = j * 1024 + t;
        unsigned h = g_hist64[b];
        if (h) atomicAdd(&sup[b >> 6], h);
    }
    __syncthreads();
    for (int off = 1; off < 1024; off <<= 1) {
        unsigned v = sup[t] + ((t + off < 1024) ? sup[t + off] : 0u);
        __syncthreads();
        sup[t] = v;
        __syncthreads();
    }
    unsigned sufHere = sup[t];
    unsigned sufNext = (t < 1023) ? sup[t + 1] : 0u;
    if (sufHere >= NCAND && sufNext < NCAND) {
        unsigned acc = sufNext;
        int T = t * 64;
        for (int b = 63; b >= 0; --b) {
            acc += g_hist64[t * 64 + b];
            if (acc >= NCAND) { T = t * 64 + b; break; }
        }
        g_prefix = ((unsigned)T) << 16;
    }
    __syncthreads();
    // self-clean: zero the histogram for the next replay
    for (int j = 0; j < 64; j++)
        g_hist64[j * 1024 + t] = 0u;
}

// ---- fused select + sort: grid selects candidates; last block bitonic-sorts ----
__global__ void k_selsort(float* __restrict__ out) {
    __shared__ unsigned long long sm[CAP];
    __shared__ int s_last;
    int tid = threadIdx.x;
    unsigned pref = g_prefix;

    int i = blockIdx.x * blockDim.x + tid;
    if (i < N_) {
        unsigned k = g_keys[i];
        if (k >= pref) {
            int p = atomicAdd(&g_selcount, 1);
            if (p < CAP)
                g_cand[p] = (((unsigned long long)k) << 32) | (unsigned)(~(unsigned)i);
        }
    }
    __threadfence();
    __syncthreads();
    if (tid == 0)
        s_last = (atomicAdd(&g_ticket, 1) == (int)gridDim.x - 1) ? 1 : 0;
    __syncthreads();
    if (!s_last) return;

    int cnt = *((volatile int*)&g_selcount); if (cnt > CAP) cnt = CAP;
    if (tid == 0) { g_selcount = 0; g_ticket = 0; }   // self-clean
    for (int s = 0; s < CAP / 1024; s++) {
        int j = tid + s * 1024;
        sm[j] = (j < cnt) ? *((volatile unsigned long long*)&g_cand[j]) : 0ull;
    }
    __syncthreads();
    for (int k = 2; k <= CAP; k <<= 1) {
        for (int j = k >> 1; j > 0; j >>= 1) {
            for (int s = 0; s < CAP / 1024; s++) {
                int a = tid + s * 1024;
                int l = a ^ j;
                if (l > a) {
                    unsigned long long va = sm[a], vb = sm[l];
                    bool up = ((a & k) == 0);
                    if ((va < vb) == up) { sm[a] = vb; sm[l] = va; }
                }
            }
            __syncthreads();
        }
    }
    unsigned idx = ~((unsigned)sm[tid]);
    out[N_ + tid] = (float)idx;
}

// ---------------- launch --------------------------------------------------------
extern "C" void kernel_launch(void* const* d_in, const int* in_sizes, int n_in,
                              void* d_out, int out_size) {
    const int*   rows   = (const int*)d_in[0];
    const int*   cols   = (const int*)d_in[1];
    const float* vals   = (const float*)d_in[2];
    const float* embeds = (const float*)d_in[3];
    float* out = (float*)d_out;

    // key chain (partitionable): key(42) -> (split) kd1 -> (split) kd2 -> (split) kn
    unsigned k0 = 0u, k1 = 42u, nk[2], kd1[2], kd2[2], kn[2];
    jax_split_part(k0, k1, nk, kd1); k0 = nk[0]; k1 = nk[1];
    jax_split_part(k0, k1, nk, kd2); k0 = nk[0]; k1 = nk[1];
    jax_split_part(k0, k1, nk, kn);

    const int B = 256;
    const int gN32 = (N_ * 32 + B - 1) / B;
    const int gE   = (E_ + B - 1) / B;
    const int gE2  = (E_ / 2 + B - 1) / B;
    const int gS   = (N_ + 1023) / 1024;

    k_count<<<gE, B>>>(rows, kd1[0], kd1[1], kd2[0], kd2[1]);
    k_scanA<<<NBLK, SCAN_B>>>();
    k_scanC<<<NBLK, SCAN_B>>>();
    k_fill<<<gE2, B>>>(rows, cols, vals);     // atomic-free, 2 edges/thread

    k_pass<1><<<gN32, B>>>((const float2*)embeds, out, kn[0], kn[1]);
    k_pass<2><<<gN32, B>>>((const float2*)embeds, out, kn[0], kn[1]);
    k_pass<3><<<gN32, B>>>((const float2*)embeds, out, kn[0], kn[1]);

    k_thresh<<<1, 1024>>>();
    k_selsort<<<gS, 1024>>>(out);
}